// round 4
// baseline (speedup 1.0000x reference)
#include <cuda_runtime.h>
#include <math.h>

// Problem dims
#define HH 160
#define WW 192
#define DD 160
#define WD (WW*DD)          // 30720
#define NV (HH*WW*DD)       // 4915200
#define NV3 (3*NV)          // 14745600
#define PAD 4
#define WINSZ 9
#define NWIN 729.0f

#define CW 32
#define WCHUNKS (WW/CW)     // 6
#define CHN 32
#define HCHUNKS (HH/CHN)    // 5
#define RS_THREADS_W (HH*DD*WCHUNKS)   // 153600
#define RS_THREADS_H (WD*HCHUNKS)      // 153600

#define RED_BLOCKS 1024

// Scratch (device globals; allocation-free per harness rules)
__device__ float g_flowA[NV3];
__device__ float g_flowB[NV3];
__device__ float g_m[NV3];
__device__ float g_v[NV3];
__device__ float g_vh[NV3];
__device__ float g_t0[NV3];   // 3-field ping
__device__ float g_t1[NV3];   // 3-field pong
__device__ float g_I[NV];     // warped image
__device__ float g_Jsum[NV];
__device__ float g_J2sum[NV];
__device__ float g_gI[NV];
__device__ double g_part[RED_BLOCKS];

// ---------------------------------------------------------------------------
__global__ void k_init(const float* __restrict__ f0) {
    int i = blockIdx.x * blockDim.x + threadIdx.x;
    if (i < NV3) {
        g_flowA[i] = f0[i];
        g_m[i] = 0.f; g_v[i] = 0.f; g_vh[i] = 0.f;
    }
}

// ---------------------------------------------------------------------------
__device__ __forceinline__ float fetchx(const float* __restrict__ x, int h, int w, int d) {
    if ((unsigned)h < HH && (unsigned)w < WW && (unsigned)d < DD)
        return __ldg(&x[(h * WW + w) * DD + d]);
    return 0.f;
}

// ---------------------------------------------------------------------------
// Fused warp + D-axis conv of (I, I*I, I*J). One block per (h,w) row.
// D-conv has no cross-row halo (zero pad), so fusion is exact.
__global__ void k_warp_convDf(const float* __restrict__ x,
                              const float* __restrict__ y, int parity) {
    int row = blockIdx.x;      // h*WW + w
    int d = threadIdx.x;       // 0..DD-1
    int base = row * DD;
    int idx = base + d;
    const float* __restrict__ flow = parity ? g_flowB : g_flowA;

    int h = row / WW;
    int w = row - h * WW;

    float ch = (float)h + flow[idx];
    float cw = (float)w + flow[NV + idx];
    float cd = (float)d + flow[2 * NV + idx];

    float fh = floorf(ch), fw = floorf(cw), fd = floorf(cd);
    int i0 = (int)fh, j0 = (int)fw, k0 = (int)fd;
    float ah = ch - fh, aw = cw - fw, ad = cd - fd;

    float v000 = fetchx(x, i0,     j0,     k0);
    float v001 = fetchx(x, i0,     j0,     k0 + 1);
    float v010 = fetchx(x, i0,     j0 + 1, k0);
    float v011 = fetchx(x, i0,     j0 + 1, k0 + 1);
    float v100 = fetchx(x, i0 + 1, j0,     k0);
    float v101 = fetchx(x, i0 + 1, j0,     k0 + 1);
    float v110 = fetchx(x, i0 + 1, j0 + 1, k0);
    float v111 = fetchx(x, i0 + 1, j0 + 1, k0 + 1);

    float wh0 = 1.f - ah, wh1 = ah;
    float ww0 = 1.f - aw, ww1 = aw;
    float wd0 = 1.f - ad, wd1 = ad;

    float val = v000 * (wh0 * ww0 * wd0) + v001 * (wh0 * ww0 * wd1)
              + v010 * (wh0 * ww1 * wd0) + v011 * (wh0 * ww1 * wd1)
              + v100 * (wh1 * ww0 * wd0) + v101 * (wh1 * ww0 * wd1)
              + v110 * (wh1 * ww1 * wd0) + v111 * (wh1 * ww1 * wd1);

    __shared__ float sI[DD + 2 * PAD];
    __shared__ float sJ[DD + 2 * PAD];
    sI[d + PAD] = val;
    sJ[d + PAD] = y[idx];
    if (d < PAD) {
        sI[d] = 0.f; sJ[d] = 0.f;
        sI[DD + PAD + d] = 0.f; sJ[DD + PAD + d] = 0.f;
    }
    __syncthreads();
    g_I[idx] = val;

    float a = 0.f, b = 0.f, c = 0.f;
#pragma unroll
    for (int j = 0; j < WINSZ; j++) {
        float iv = sI[d + j], jv = sJ[d + j];
        a += iv; b += iv * iv; c += iv * jv;
    }
    g_t0[idx] = a;
    g_t0[NV + idx] = b;
    g_t0[2 * NV + idx] = c;
}

// Generic 3-field D conv: t0 -> t1 (adjoint D pass)
__global__ void k_convD_3() {
    int row = blockIdx.x;
    int d = threadIdx.x;
    __shared__ float s0[DD + 2 * PAD];
    __shared__ float s1[DD + 2 * PAD];
    __shared__ float s2[DD + 2 * PAD];
    int base = row * DD;
    s0[d + PAD] = g_t0[base + d];
    s1[d + PAD] = g_t0[NV + base + d];
    s2[d + PAD] = g_t0[2 * NV + base + d];
    if (d < PAD) {
        s0[d] = s1[d] = s2[d] = 0.f;
        s0[DD + PAD + d] = s1[DD + PAD + d] = s2[DD + PAD + d] = 0.f;
    }
    __syncthreads();
    float a = 0.f, b = 0.f, c = 0.f;
#pragma unroll
    for (int j = 0; j < WINSZ; j++) { a += s0[d + j]; b += s1[d + j]; c += s2[d + j]; }
    g_t1[base + d] = a;
    g_t1[NV + base + d] = b;
    g_t1[2 * NV + base + d] = c;
}

// J-precompute D pass: fields (J, J*J) -> t0 fields 0,1
__global__ void k_convD_J(const float* __restrict__ y) {
    int row = blockIdx.x;
    int d = threadIdx.x;
    __shared__ float sJ[DD + 2 * PAD];
    int base = row * DD;
    sJ[d + PAD] = y[base + d];
    if (d < PAD) { sJ[d] = 0.f; sJ[DD + PAD + d] = 0.f; }
    __syncthreads();
    float a = 0.f, b = 0.f;
#pragma unroll
    for (int j = 0; j < WINSZ; j++) { float jv = sJ[d + j]; a += jv; b += jv * jv; }
    g_t0[base + d] = a;
    g_t0[NV + base + d] = b;
}

// ---------------------------------------------------------------------------
// W-axis running-sum conv, 3 fields. dir=0: t0->t1, dir=1: t1->t0.
__global__ void k_convW3_rs(int dir) {
    int tid = blockIdx.x * blockDim.x + threadIdx.x;
    if (tid >= RS_THREADS_W) return;
    int d = tid % DD;
    int t2 = tid / DD;
    int h = t2 % HH;
    int chunk = t2 / HH;
    const float* __restrict__ src = dir ? g_t1 : g_t0;
    float* __restrict__ dst = dir ? g_t0 : g_t1;

    int base = h * WD + d;
    int w0 = chunk * CW;
    float sA = 0.f, sB = 0.f, sC = 0.f;
#pragma unroll
    for (int j = -PAD; j <= PAD; j++) {
        int wq = w0 + j;
        if ((unsigned)wq < WW) {
            int q = base + wq * DD;
            sA += src[q]; sB += src[NV + q]; sC += src[2 * NV + q];
        }
    }
    for (int w = w0; w < w0 + CW; w++) {
        int q = base + w * DD;
        dst[q] = sA; dst[NV + q] = sB; dst[2 * NV + q] = sC;
        int wn = w + PAD + 1, wo = w - PAD;
        if (wn < WW) {
            int qn = base + wn * DD;
            sA += src[qn]; sB += src[NV + qn]; sC += src[2 * NV + qn];
        }
        if (wo >= 0) {
            int qo = base + wo * DD;
            sA -= src[qo]; sB -= src[NV + qo]; sC -= src[2 * NV + qo];
        }
    }
}

// 2-field W running-sum for J precompute: t0 -> t1
__global__ void k_convW2_rs() {
    int tid = blockIdx.x * blockDim.x + threadIdx.x;
    if (tid >= RS_THREADS_W) return;
    int d = tid % DD;
    int t2 = tid / DD;
    int h = t2 % HH;
    int chunk = t2 / HH;
    int base = h * WD + d;
    int w0 = chunk * CW;
    float sA = 0.f, sB = 0.f;
#pragma unroll
    for (int j = -PAD; j <= PAD; j++) {
        int wq = w0 + j;
        if ((unsigned)wq < WW) {
            int q = base + wq * DD;
            sA += g_t0[q]; sB += g_t0[NV + q];
        }
    }
    for (int w = w0; w < w0 + CW; w++) {
        int q = base + w * DD;
        g_t1[q] = sA; g_t1[NV + q] = sB;
        int wn = w + PAD + 1, wo = w - PAD;
        if (wn < WW) { int qn = base + wn * DD; sA += g_t0[qn]; sB += g_t0[NV + qn]; }
        if (wo >= 0) { int qo = base + wo * DD; sA -= g_t0[qo]; sB -= g_t0[NV + qo]; }
    }
}

// 2-field H running-sum for J precompute: t1 -> (Jsum, J2sum)
__global__ void k_convH2_rs() {
    int tid = blockIdx.x * blockDim.x + threadIdx.x;
    if (tid >= RS_THREADS_H) return;
    int col = tid % WD;
    int chunk = tid / WD;
    int h0 = chunk * CHN;
    float sA = 0.f, sB = 0.f;
#pragma unroll
    for (int j = -PAD; j <= PAD; j++) {
        int hq = h0 + j;
        if ((unsigned)hq < HH) {
            int q = hq * WD + col;
            sA += g_t1[q]; sB += g_t1[NV + q];
        }
    }
    for (int h = h0; h < h0 + CHN; h++) {
        int q = h * WD + col;
        g_Jsum[q] = sA; g_J2sum[q] = sB;
        int hn = h + PAD + 1, ho = h - PAD;
        if (hn < HH) { int qn = hn * WD + col; sA += g_t1[qn]; sB += g_t1[NV + qn]; }
        if (ho >= 0) { int qo = ho * WD + col; sA -= g_t1[qo]; sB -= g_t1[NV + qo]; }
    }
}

// ---------------------------------------------------------------------------
// H-axis running-sum conv (forward) fused with NCC adjoint coefficients.
// Reads t1 (3 fields), writes t0 (gA, gC, gE).
__global__ void k_convH_coeff_rs() {
    int tid = blockIdx.x * blockDim.x + threadIdx.x;
    if (tid >= RS_THREADS_H) return;
    int col = tid % WD;
    int chunk = tid / WD;
    int h0 = chunk * CHN;
    float A = 0.f, C = 0.f, E = 0.f;
#pragma unroll
    for (int j = -PAD; j <= PAD; j++) {
        int hq = h0 + j;
        if ((unsigned)hq < HH) {
            int q = hq * WD + col;
            A += g_t1[q]; C += g_t1[NV + q]; E += g_t1[2 * NV + q];
        }
    }
    const float s = -1.f / (float)NV;
    for (int h = h0; h < h0 + CHN; h++) {
        int idx = h * WD + col;
        float B  = g_Jsum[idx];
        float Dv = g_J2sum[idx];
        float uI = A * (1.f / NWIN);
        float uJ = B * (1.f / NWIN);
        float cross = E - uJ * A - uI * B + uI * uJ * NWIN;
        float Ivar  = C - 2.f * uI * A + uI * uI * NWIN;
        float Jvar  = Dv - 2.f * uJ * B + uJ * uJ * NWIN;
        float denom = Ivar * Jvar + 1e-5f;
        float r = cross / denom;
        float gE = s * 2.f * r;
        float gC = -s * (r * r) * Jvar;
        float gA = s * (-2.f * r * uJ + 2.f * (r * r) * Jvar * uI);
        g_t0[idx] = gA;
        g_t0[NV + idx] = gC;
        g_t0[2 * NV + idx] = gE;

        int hn = h + PAD + 1, ho = h - PAD;
        if (hn < HH) {
            int qn = hn * WD + col;
            A += g_t1[qn]; C += g_t1[NV + qn]; E += g_t1[2 * NV + qn];
        }
        if (ho >= 0) {
            int qo = ho * WD + col;
            A -= g_t1[qo]; C -= g_t1[NV + qo]; E -= g_t1[2 * NV + qo];
        }
    }
}

// H-axis running-sum conv (backward) fused with gI assembly.
// Reads t0 (W[gA..] partial), writes g_gI.
__global__ void k_convH_gI_rs(const float* __restrict__ y) {
    int tid = blockIdx.x * blockDim.x + threadIdx.x;
    if (tid >= RS_THREADS_H) return;
    int col = tid % WD;
    int chunk = tid / WD;
    int h0 = chunk * CHN;
    float wa = 0.f, wc = 0.f, we = 0.f;
#pragma unroll
    for (int j = -PAD; j <= PAD; j++) {
        int hq = h0 + j;
        if ((unsigned)hq < HH) {
            int q = hq * WD + col;
            wa += g_t0[q]; wc += g_t0[NV + q]; we += g_t0[2 * NV + q];
        }
    }
    for (int h = h0; h < h0 + CHN; h++) {
        int idx = h * WD + col;
        g_gI[idx] = wa + 2.f * g_I[idx] * wc + y[idx] * we;
        int hn = h + PAD + 1, ho = h - PAD;
        if (hn < HH) {
            int qn = hn * WD + col;
            wa += g_t0[qn]; wc += g_t0[NV + qn]; we += g_t0[2 * NV + qn];
        }
        if (ho >= 0) {
            int qo = ho * WD + col;
            wa -= g_t0[qo]; wc -= g_t0[NV + qo]; we -= g_t0[2 * NV + qo];
        }
    }
}

// ---------------------------------------------------------------------------
// Fused gradient + Adam(amsgrad): reads flow_cur (incl. neighbors), writes flow_nxt.
__global__ void k_grad_adam(const float* __restrict__ x, int parity,
                            float bc1, float sbc2) {
    int idx = blockIdx.x * blockDim.x + threadIdx.x;
    if (idx >= NV) return;
    const float* __restrict__ cur = parity ? g_flowB : g_flowA;
    float* __restrict__ nxt = parity ? g_flowA : g_flowB;

    int h = idx / WD;
    int r = idx - h * WD;
    int w = r / DD;
    int d = r - w * DD;

    float fH = cur[idx];
    float fW = cur[NV + idx];
    float fD = cur[2 * NV + idx];

    float ch = (float)h + fH;
    float cw = (float)w + fW;
    float cd = (float)d + fD;
    float fh = floorf(ch), fw = floorf(cw), fd = floorf(cd);
    int i0 = (int)fh, j0 = (int)fw, k0 = (int)fd;
    float ah = ch - fh, aw = cw - fw, ad = cd - fd;

    float v000 = fetchx(x, i0,     j0,     k0);
    float v001 = fetchx(x, i0,     j0,     k0 + 1);
    float v010 = fetchx(x, i0,     j0 + 1, k0);
    float v011 = fetchx(x, i0,     j0 + 1, k0 + 1);
    float v100 = fetchx(x, i0 + 1, j0,     k0);
    float v101 = fetchx(x, i0 + 1, j0,     k0 + 1);
    float v110 = fetchx(x, i0 + 1, j0 + 1, k0);
    float v111 = fetchx(x, i0 + 1, j0 + 1, k0 + 1);

    float wh0 = 1.f - ah, wh1 = ah;
    float ww0 = 1.f - aw, ww1 = aw;
    float wd0 = 1.f - ad, wd1 = ad;

    float dch = ww0 * wd0 * (v100 - v000) + ww0 * wd1 * (v101 - v001)
              + ww1 * wd0 * (v110 - v010) + ww1 * wd1 * (v111 - v011);
    float dcw = wh0 * wd0 * (v010 - v000) + wh0 * wd1 * (v011 - v001)
              + wh1 * wd0 * (v110 - v100) + wh1 * wd1 * (v111 - v101);
    float dcd = wh0 * ww0 * (v001 - v000) + wh0 * ww1 * (v011 - v010)
              + wh1 * ww0 * (v101 - v100) + wh1 * ww1 * (v111 - v110);

    float gi = g_gI[idx];

    const float coefH = 2.f / (3.f * (float)(3 * (HH - 1) * WW * DD));
    const float coefW = 2.f / (3.f * (float)(3 * HH * (WW - 1) * DD));
    const float coefD = 2.f / (3.f * (float)(3 * HH * WW * (DD - 1)));

    float dint[3] = { dch, dcw, dcd };
#pragma unroll
    for (int c = 0; c < 3; c++) {
        int off = c * NV + idx;
        float fc = (c == 0) ? fH : (c == 1) ? fW : fD;
        float tH = 0.f, tW = 0.f, tD = 0.f;
        if (h > 0)      tH += fc - cur[off - WD];
        if (h < HH - 1) tH -= cur[off + WD] - fc;
        if (w > 0)      tW += fc - cur[off - DD];
        if (w < WW - 1) tW -= cur[off + DD] - fc;
        if (d > 0)      tD += fc - cur[off - 1];
        if (d < DD - 1) tD -= cur[off + 1] - fc;
        float g = gi * dint[c] + coefH * tH + coefW * tW + coefD * tD;

        float m = 0.9f * g_m[off] + 0.1f * g;
        float v = 0.999f * g_v[off] + 0.001f * g * g;
        float vh = fmaxf(g_vh[off], v);
        g_m[off] = m; g_v[off] = v; g_vh[off] = vh;
        float m_hat = m / bc1;
        float denom = sqrtf(vh) / sbc2 + 1e-8f;
        nxt[off] = fc - 0.1f * m_hat / denom;
    }
}

// ---------------------------------------------------------------------------
// Final MSE: deterministic two-stage reduction (double accumulation).
__global__ void k_mse_part(const float* __restrict__ f0, int finalB) {
    const float* __restrict__ flow = finalB ? g_flowB : g_flowA;
    __shared__ double sd[256];
    double acc = 0.0;
    for (int i = blockIdx.x * blockDim.x + threadIdx.x; i < NV3;
         i += gridDim.x * blockDim.x) {
        float dlt = flow[i] - f0[i];
        acc += (double)dlt * (double)dlt;
    }
    sd[threadIdx.x] = acc;
    __syncthreads();
    for (int st = 128; st > 0; st >>= 1) {
        if (threadIdx.x < st) sd[threadIdx.x] += sd[threadIdx.x + st];
        __syncthreads();
    }
    if (threadIdx.x == 0) g_part[blockIdx.x] = sd[0];
}

__global__ void k_mse_final(float* __restrict__ out) {
    __shared__ double sd[256];
    double acc = 0.0;
    for (int i = threadIdx.x; i < RED_BLOCKS; i += 256) acc += g_part[i];
    sd[threadIdx.x] = acc;
    __syncthreads();
    for (int st = 128; st > 0; st >>= 1) {
        if (threadIdx.x < st) sd[threadIdx.x] += sd[threadIdx.x + st];
        __syncthreads();
    }
    if (threadIdx.x == 0) out[0] = (float)(sd[0] / (double)NV3);
}

// ---------------------------------------------------------------------------
extern "C" void kernel_launch(void* const* d_in, const int* in_sizes, int n_in,
                              void* d_out, int out_size) {
    const float* x  = (const float*)d_in[0];
    const float* y  = (const float*)d_in[1];
    const float* f0 = (const float*)d_in[2];
    float* out = (float*)d_out;
    (void)in_sizes; (void)n_in; (void)out_size;

    const int NB  = (NV  + 255) / 256;
    const int NB3 = (NV3 + 255) / 256;
    const int NBW = (RS_THREADS_W + 255) / 256;   // 600
    const int NBH = (RS_THREADS_H + 255) / 256;   // 600

    k_init<<<NB3, 256>>>(f0);

    // Precompute J window sums (constant across Adam steps)
    k_convD_J<<<HH * WW, DD>>>(y);
    k_convW2_rs<<<NBW, 256>>>();
    k_convH2_rs<<<NBH, 256>>>();

    for (int t = 1; t <= 5; t++) {
        int parity = (t - 1) & 1;
        k_warp_convDf<<<HH * WW, DD>>>(x, y, parity);   // -> t0 (I,I2,IJ D-conv), g_I
        k_convW3_rs<<<NBW, 256>>>(0);                   // t0 -> t1
        k_convH_coeff_rs<<<NBH, 256>>>();               // t1 -> t0 (gA,gC,gE)
        k_convD_3<<<HH * WW, DD>>>();                   // t0 -> t1
        k_convW3_rs<<<NBW, 256>>>(1);                   // t1 -> t0
        k_convH_gI_rs<<<NBH, 256>>>(y);                 // t0 -> gI
        double bc1 = 1.0 - pow(0.9, (double)t);
        double bc2 = 1.0 - pow(0.999, (double)t);
        k_grad_adam<<<NB, 256>>>(x, parity, (float)bc1, (float)sqrt(bc2));
    }

    k_mse_part<<<RED_BLOCKS, 256>>>(f0, 1);   // final flow in B after 5 iters
    k_mse_final<<<1, 256>>>(out);
}

// round 5
// speedup vs baseline: 1.3567x; 1.3567x over previous
#include <cuda_runtime.h>
#include <math.h>

// Problem dims
#define HH 160
#define WW 192
#define DD 160
#define WD (WW*DD)          // 30720
#define NV (HH*WW*DD)       // 4915200
#define NV3 (3*NV)          // 14745600
#define PAD 4
#define WINSZ 9
#define NWIN 729.0f

#define D4 (DD/4)           // 40
#define CW4 16
#define WCH (WW/CW4)        // 12
#define CH4 16
#define HCH (HH/CH4)        // 10
#define RS4_W (HH*D4*WCH)   // 76800
#define RS4_H ((WD/4)*HCH)  // 76800

#define RED_BLOCKS 1024

// Scratch (device globals; allocation-free per harness rules)
__device__ float g_flowA[NV3];
__device__ float g_flowB[NV3];
__device__ float g_m[NV3];
__device__ float g_v[NV3];
__device__ float g_vh[NV3];
__device__ float g_t0[NV3];   // 3-field ping
__device__ float g_t1[NV3];   // 3-field pong
__device__ float g_I[NV];     // warped image
__device__ float g_Jsum[NV];
__device__ float g_J2sum[NV];
__device__ float g_gI[NV];
__device__ double g_part[RED_BLOCKS];

// ---------------------------------------------------------------------------
__device__ __forceinline__ float4 ld4(const float* p) {
    return *reinterpret_cast<const float4*>(p);
}
__device__ __forceinline__ void st4(float* p, float4 v) {
    *reinterpret_cast<float4*>(p) = v;
}
__device__ __forceinline__ float4 f4add(float4 a, float4 b) {
    return make_float4(a.x + b.x, a.y + b.y, a.z + b.z, a.w + b.w);
}
__device__ __forceinline__ float4 f4sub(float4 a, float4 b) {
    return make_float4(a.x - b.x, a.y - b.y, a.z - b.z, a.w - b.w);
}

// ---------------------------------------------------------------------------
__global__ void k_init4(const float* __restrict__ f0) {
    int i = (blockIdx.x * blockDim.x + threadIdx.x) * 4;
    if (i < NV3) {
        st4(g_flowA + i, ld4(f0 + i));
        float4 z = make_float4(0.f, 0.f, 0.f, 0.f);
        st4(g_m + i, z); st4(g_v + i, z); st4(g_vh + i, z);
    }
}

// ---------------------------------------------------------------------------
__device__ __forceinline__ float fetchx(const float* __restrict__ x, int h, int w, int d) {
    if ((unsigned)h < HH && (unsigned)w < WW && (unsigned)d < DD)
        return __ldg(&x[(h * WW + w) * DD + d]);
    return 0.f;
}

// ---------------------------------------------------------------------------
// Fused warp + D-axis conv of (I, I*I, I*J). One block per (h,w) row.
__global__ void k_warp_convDf(const float* __restrict__ x,
                              const float* __restrict__ y, int parity) {
    int row = blockIdx.x;      // h*WW + w
    int d = threadIdx.x;       // 0..DD-1
    int base = row * DD;
    int idx = base + d;
    const float* __restrict__ flow = parity ? g_flowB : g_flowA;

    int h = row / WW;
    int w = row - h * WW;

    float ch = (float)h + flow[idx];
    float cw = (float)w + flow[NV + idx];
    float cd = (float)d + flow[2 * NV + idx];

    float fh = floorf(ch), fw = floorf(cw), fd = floorf(cd);
    int i0 = (int)fh, j0 = (int)fw, k0 = (int)fd;
    float ah = ch - fh, aw = cw - fw, ad = cd - fd;

    float v000 = fetchx(x, i0,     j0,     k0);
    float v001 = fetchx(x, i0,     j0,     k0 + 1);
    float v010 = fetchx(x, i0,     j0 + 1, k0);
    float v011 = fetchx(x, i0,     j0 + 1, k0 + 1);
    float v100 = fetchx(x, i0 + 1, j0,     k0);
    float v101 = fetchx(x, i0 + 1, j0,     k0 + 1);
    float v110 = fetchx(x, i0 + 1, j0 + 1, k0);
    float v111 = fetchx(x, i0 + 1, j0 + 1, k0 + 1);

    float wh0 = 1.f - ah, wh1 = ah;
    float ww0 = 1.f - aw, ww1 = aw;
    float wd0 = 1.f - ad, wd1 = ad;

    float val = v000 * (wh0 * ww0 * wd0) + v001 * (wh0 * ww0 * wd1)
              + v010 * (wh0 * ww1 * wd0) + v011 * (wh0 * ww1 * wd1)
              + v100 * (wh1 * ww0 * wd0) + v101 * (wh1 * ww0 * wd1)
              + v110 * (wh1 * ww1 * wd0) + v111 * (wh1 * ww1 * wd1);

    __shared__ float sI[DD + 2 * PAD];
    __shared__ float sJ[DD + 2 * PAD];
    sI[d + PAD] = val;
    sJ[d + PAD] = y[idx];
    if (d < PAD) {
        sI[d] = 0.f; sJ[d] = 0.f;
        sI[DD + PAD + d] = 0.f; sJ[DD + PAD + d] = 0.f;
    }
    __syncthreads();
    g_I[idx] = val;

    float a = 0.f, b = 0.f, c = 0.f;
#pragma unroll
    for (int j = 0; j < WINSZ; j++) {
        float iv = sI[d + j], jv = sJ[d + j];
        a += iv; b += iv * iv; c += iv * jv;
    }
    g_t0[idx] = a;
    g_t0[NV + idx] = b;
    g_t0[2 * NV + idx] = c;
}

// ---------------------------------------------------------------------------
// 3-field D conv (adjoint), float4 loads, 4 rows per block. t0 -> t1.
__global__ void k_convD_3v() {
    __shared__ __align__(16) float s0[4][DD + 2 * PAD];
    __shared__ __align__(16) float s1[4][DD + 2 * PAD];
    __shared__ __align__(16) float s2[4][DD + 2 * PAD];
    int r = threadIdx.x / D4;      // row within block 0..3
    int i = threadIdx.x % D4;      // float4 index 0..39
    int row = blockIdx.x * 4 + r;
    int base = row * DD;
    int q = base + i * 4;

    st4(&s0[r][PAD + i * 4], ld4(g_t0 + q));
    st4(&s1[r][PAD + i * 4], ld4(g_t0 + NV + q));
    st4(&s2[r][PAD + i * 4], ld4(g_t0 + 2 * NV + q));
    if (i == 0) {
#pragma unroll
        for (int j = 0; j < PAD; j++) {
            s0[r][j] = 0.f; s1[r][j] = 0.f; s2[r][j] = 0.f;
            s0[r][DD + PAD + j] = 0.f; s1[r][DD + PAD + j] = 0.f; s2[r][DD + PAD + j] = 0.f;
        }
    }
    __syncthreads();

    float4 o0, o1, o2;
    float* p0 = &o0.x; float* p1 = &o1.x; float* p2 = &o2.x;
#pragma unroll
    for (int l = 0; l < 4; l++) {
        int d = i * 4 + l;
        float a = 0.f, b = 0.f, c = 0.f;
#pragma unroll
        for (int j = 0; j < WINSZ; j++) {
            a += s0[r][d + j]; b += s1[r][d + j]; c += s2[r][d + j];
        }
        p0[l] = a; p1[l] = b; p2[l] = c;
    }
    st4(g_t1 + q, o0);
    st4(g_t1 + NV + q, o1);
    st4(g_t1 + 2 * NV + q, o2);
}

// J-precompute D pass: fields (J, J*J) -> t0 fields 0,1
__global__ void k_convD_J(const float* __restrict__ y) {
    int row = blockIdx.x;
    int d = threadIdx.x;
    __shared__ float sJ[DD + 2 * PAD];
    int base = row * DD;
    sJ[d + PAD] = y[base + d];
    if (d < PAD) { sJ[d] = 0.f; sJ[DD + PAD + d] = 0.f; }
    __syncthreads();
    float a = 0.f, b = 0.f;
#pragma unroll
    for (int j = 0; j < WINSZ; j++) { float jv = sJ[d + j]; a += jv; b += jv * jv; }
    g_t0[base + d] = a;
    g_t0[NV + base + d] = b;
}

// ---------------------------------------------------------------------------
// W-axis running-sum conv, float4, 3 fields. dir=0: t0->t1, dir=1: t1->t0.
__global__ void k_convW3_rs4(int dir) {
    int tid = blockIdx.x * blockDim.x + threadIdx.x;
    if (tid >= RS4_W) return;
    int d4 = tid % D4;
    int t2 = tid / D4;
    int h = t2 % HH;
    int chunk = t2 / HH;
    const float* __restrict__ src = dir ? g_t1 : g_t0;
    float* __restrict__ dst = dir ? g_t0 : g_t1;

    int base = h * WD + d4 * 4;
    int w0 = chunk * CW4;
    float4 sA = make_float4(0.f, 0.f, 0.f, 0.f), sB = sA, sC = sA;
#pragma unroll
    for (int j = -PAD; j <= PAD; j++) {
        int wq = w0 + j;
        if ((unsigned)wq < WW) {
            int q = base + wq * DD;
            sA = f4add(sA, ld4(src + q));
            sB = f4add(sB, ld4(src + NV + q));
            sC = f4add(sC, ld4(src + 2 * NV + q));
        }
    }
#pragma unroll
    for (int w = 0; w < CW4; w++) {
        int wc = w0 + w;
        int q = base + wc * DD;
        st4(dst + q, sA); st4(dst + NV + q, sB); st4(dst + 2 * NV + q, sC);
        int wn = wc + PAD + 1, wo = wc - PAD;
        if (wn < WW) {
            int qn = base + wn * DD;
            sA = f4add(sA, ld4(src + qn));
            sB = f4add(sB, ld4(src + NV + qn));
            sC = f4add(sC, ld4(src + 2 * NV + qn));
        }
        if (wo >= 0) {
            int qo = base + wo * DD;
            sA = f4sub(sA, ld4(src + qo));
            sB = f4sub(sB, ld4(src + NV + qo));
            sC = f4sub(sC, ld4(src + 2 * NV + qo));
        }
    }
}

// 2-field W running-sum (J precompute): t0 -> t1
__global__ void k_convW2_rs4() {
    int tid = blockIdx.x * blockDim.x + threadIdx.x;
    if (tid >= RS4_W) return;
    int d4 = tid % D4;
    int t2 = tid / D4;
    int h = t2 % HH;
    int chunk = t2 / HH;
    int base = h * WD + d4 * 4;
    int w0 = chunk * CW4;
    float4 sA = make_float4(0.f, 0.f, 0.f, 0.f), sB = sA;
#pragma unroll
    for (int j = -PAD; j <= PAD; j++) {
        int wq = w0 + j;
        if ((unsigned)wq < WW) {
            int q = base + wq * DD;
            sA = f4add(sA, ld4(g_t0 + q));
            sB = f4add(sB, ld4(g_t0 + NV + q));
        }
    }
#pragma unroll
    for (int w = 0; w < CW4; w++) {
        int wc = w0 + w;
        int q = base + wc * DD;
        st4(g_t1 + q, sA); st4(g_t1 + NV + q, sB);
        int wn = wc + PAD + 1, wo = wc - PAD;
        if (wn < WW) {
            int qn = base + wn * DD;
            sA = f4add(sA, ld4(g_t0 + qn)); sB = f4add(sB, ld4(g_t0 + NV + qn));
        }
        if (wo >= 0) {
            int qo = base + wo * DD;
            sA = f4sub(sA, ld4(g_t0 + qo)); sB = f4sub(sB, ld4(g_t0 + NV + qo));
        }
    }
}

// 2-field H running-sum (J precompute): t1 -> (Jsum, J2sum)
__global__ void k_convH2_rs4() {
    int tid = blockIdx.x * blockDim.x + threadIdx.x;
    if (tid >= RS4_H) return;
    int c4 = tid % (WD / 4);
    int chunk = tid / (WD / 4);
    int col = c4 * 4;
    int h0 = chunk * CH4;
    float4 sA = make_float4(0.f, 0.f, 0.f, 0.f), sB = sA;
#pragma unroll
    for (int j = -PAD; j <= PAD; j++) {
        int hq = h0 + j;
        if ((unsigned)hq < HH) {
            int q = hq * WD + col;
            sA = f4add(sA, ld4(g_t1 + q));
            sB = f4add(sB, ld4(g_t1 + NV + q));
        }
    }
#pragma unroll
    for (int hh = 0; hh < CH4; hh++) {
        int h = h0 + hh;
        int q = h * WD + col;
        st4(g_Jsum + q, sA); st4(g_J2sum + q, sB);
        int hn = h + PAD + 1, ho = h - PAD;
        if (hn < HH) {
            int qn = hn * WD + col;
            sA = f4add(sA, ld4(g_t1 + qn)); sB = f4add(sB, ld4(g_t1 + NV + qn));
        }
        if (ho >= 0) {
            int qo = ho * WD + col;
            sA = f4sub(sA, ld4(g_t1 + qo)); sB = f4sub(sB, ld4(g_t1 + NV + qo));
        }
    }
}

// ---------------------------------------------------------------------------
__device__ __forceinline__ void ncc_coeff(float A, float B, float C, float Dv,
                                          float E, float& gA, float& gC, float& gE) {
    const float s = -1.f / (float)NV;
    float uI = A * (1.f / NWIN);
    float uJ = B * (1.f / NWIN);
    float cross = E - uJ * A - uI * B + uI * uJ * NWIN;
    float Ivar  = C - 2.f * uI * A + uI * uI * NWIN;
    float Jvar  = Dv - 2.f * uJ * B + uJ * uJ * NWIN;
    float denom = Ivar * Jvar + 1e-5f;
    float r = cross / denom;
    gE = s * 2.f * r;
    gC = -s * (r * r) * Jvar;
    gA = s * (-2.f * r * uJ + 2.f * (r * r) * Jvar * uI);
}

// H running-sum (forward) fused with NCC adjoint coefficients. t1 -> t0.
__global__ void k_convH_coeff_rs4() {
    int tid = blockIdx.x * blockDim.x + threadIdx.x;
    if (tid >= RS4_H) return;
    int c4 = tid % (WD / 4);
    int chunk = tid / (WD / 4);
    int col = c4 * 4;
    int h0 = chunk * CH4;
    float4 A4 = make_float4(0.f, 0.f, 0.f, 0.f), C4 = A4, E4 = A4;
#pragma unroll
    for (int j = -PAD; j <= PAD; j++) {
        int hq = h0 + j;
        if ((unsigned)hq < HH) {
            int q = hq * WD + col;
            A4 = f4add(A4, ld4(g_t1 + q));
            C4 = f4add(C4, ld4(g_t1 + NV + q));
            E4 = f4add(E4, ld4(g_t1 + 2 * NV + q));
        }
    }
#pragma unroll
    for (int hh = 0; hh < CH4; hh++) {
        int h = h0 + hh;
        int idx = h * WD + col;
        float4 B4 = ld4(g_Jsum + idx);
        float4 D4v = ld4(g_J2sum + idx);
        float4 oA, oC, oE;
        const float* a = &A4.x; const float* c = &C4.x; const float* e = &E4.x;
        const float* b = &B4.x; const float* dv = &D4v.x;
        float* pa = &oA.x; float* pc = &oC.x; float* pe = &oE.x;
#pragma unroll
        for (int l = 0; l < 4; l++)
            ncc_coeff(a[l], b[l], c[l], dv[l], e[l], pa[l], pc[l], pe[l]);
        st4(g_t0 + idx, oA);
        st4(g_t0 + NV + idx, oC);
        st4(g_t0 + 2 * NV + idx, oE);

        int hn = h + PAD + 1, ho = h - PAD;
        if (hn < HH) {
            int qn = hn * WD + col;
            A4 = f4add(A4, ld4(g_t1 + qn));
            C4 = f4add(C4, ld4(g_t1 + NV + qn));
            E4 = f4add(E4, ld4(g_t1 + 2 * NV + qn));
        }
        if (ho >= 0) {
            int qo = ho * WD + col;
            A4 = f4sub(A4, ld4(g_t1 + qo));
            C4 = f4sub(C4, ld4(g_t1 + NV + qo));
            E4 = f4sub(E4, ld4(g_t1 + 2 * NV + qo));
        }
    }
}

// H running-sum (backward) fused with gI assembly. t0 -> gI.
__global__ void k_convH_gI_rs4(const float* __restrict__ y) {
    int tid = blockIdx.x * blockDim.x + threadIdx.x;
    if (tid >= RS4_H) return;
    int c4 = tid % (WD / 4);
    int chunk = tid / (WD / 4);
    int col = c4 * 4;
    int h0 = chunk * CH4;
    float4 wa = make_float4(0.f, 0.f, 0.f, 0.f), wc = wa, we = wa;
#pragma unroll
    for (int j = -PAD; j <= PAD; j++) {
        int hq = h0 + j;
        if ((unsigned)hq < HH) {
            int q = hq * WD + col;
            wa = f4add(wa, ld4(g_t0 + q));
            wc = f4add(wc, ld4(g_t0 + NV + q));
            we = f4add(we, ld4(g_t0 + 2 * NV + q));
        }
    }
#pragma unroll
    for (int hh = 0; hh < CH4; hh++) {
        int h = h0 + hh;
        int idx = h * WD + col;
        float4 I4 = ld4(g_I + idx);
        float4 y4 = ld4(y + idx);
        float4 o;
        o.x = wa.x + 2.f * I4.x * wc.x + y4.x * we.x;
        o.y = wa.y + 2.f * I4.y * wc.y + y4.y * we.y;
        o.z = wa.z + 2.f * I4.z * wc.z + y4.z * we.z;
        o.w = wa.w + 2.f * I4.w * wc.w + y4.w * we.w;
        st4(g_gI + idx, o);

        int hn = h + PAD + 1, ho = h - PAD;
        if (hn < HH) {
            int qn = hn * WD + col;
            wa = f4add(wa, ld4(g_t0 + qn));
            wc = f4add(wc, ld4(g_t0 + NV + qn));
            we = f4add(we, ld4(g_t0 + 2 * NV + qn));
        }
        if (ho >= 0) {
            int qo = ho * WD + col;
            wa = f4sub(wa, ld4(g_t0 + qo));
            wc = f4sub(wc, ld4(g_t0 + NV + qo));
            we = f4sub(we, ld4(g_t0 + 2 * NV + qo));
        }
    }
}

// ---------------------------------------------------------------------------
// Fused gradient + Adam(amsgrad), float4: 4 voxels/thread.
__global__ void k_grad_adam4(const float* __restrict__ x, int parity,
                             float bc1, float sbc2) {
    int t = blockIdx.x * blockDim.x + threadIdx.x;
    if (t >= NV / 4) return;
    int idx = t * 4;
    const float* __restrict__ cur = parity ? g_flowB : g_flowA;
    float* __restrict__ nxt = parity ? g_flowA : g_flowB;

    int h = idx / WD;
    int r = idx - h * WD;
    int w = r / DD;
    int d0 = r - w * DD;

    float4 fH4 = ld4(cur + idx);
    float4 fW4 = ld4(cur + NV + idx);
    float4 fD4 = ld4(cur + 2 * NV + idx);
    float4 gi4 = ld4(g_gI + idx);
    const float* fH = &fH4.x; const float* fW = &fW4.x; const float* fD = &fD4.x;
    const float* gi = &gi4.x;

    // Gather derivatives per lane
    float dch[4], dcw[4], dcd[4];
#pragma unroll
    for (int l = 0; l < 4; l++) {
        float ch = (float)h + fH[l];
        float cw = (float)w + fW[l];
        float cd = (float)(d0 + l) + fD[l];
        float fh = floorf(ch), fw_ = floorf(cw), fd = floorf(cd);
        int i0 = (int)fh, j0 = (int)fw_, k0 = (int)fd;
        float ah = ch - fh, aw = cw - fw_, ad = cd - fd;

        float v000 = fetchx(x, i0,     j0,     k0);
        float v001 = fetchx(x, i0,     j0,     k0 + 1);
        float v010 = fetchx(x, i0,     j0 + 1, k0);
        float v011 = fetchx(x, i0,     j0 + 1, k0 + 1);
        float v100 = fetchx(x, i0 + 1, j0,     k0);
        float v101 = fetchx(x, i0 + 1, j0,     k0 + 1);
        float v110 = fetchx(x, i0 + 1, j0 + 1, k0);
        float v111 = fetchx(x, i0 + 1, j0 + 1, k0 + 1);

        float wh0 = 1.f - ah, wh1 = ah;
        float ww0 = 1.f - aw, ww1 = aw;
        float wd0 = 1.f - ad, wd1 = ad;

        dch[l] = ww0 * wd0 * (v100 - v000) + ww0 * wd1 * (v101 - v001)
               + ww1 * wd0 * (v110 - v010) + ww1 * wd1 * (v111 - v011);
        dcw[l] = wh0 * wd0 * (v010 - v000) + wh0 * wd1 * (v011 - v001)
               + wh1 * wd0 * (v110 - v100) + wh1 * wd1 * (v111 - v101);
        dcd[l] = wh0 * ww0 * (v001 - v000) + wh0 * ww1 * (v011 - v010)
               + wh1 * ww0 * (v101 - v100) + wh1 * ww1 * (v111 - v110);
    }

    const float coefH = 2.f / (3.f * (float)(3 * (HH - 1) * WW * DD));
    const float coefW = 2.f / (3.f * (float)(3 * HH * (WW - 1) * DD));
    const float coefD = 2.f / (3.f * (float)(3 * HH * WW * (DD - 1)));

    bool hm = (h > 0), hp = (h < HH - 1);
    bool wm = (w > 0), wp = (w < WW - 1);
    bool dmL = (d0 > 0);              // left scalar exists
    bool dpR = (d0 + 4 < DD);         // right scalar exists

#pragma unroll
    for (int c = 0; c < 3; c++) {
        int off = c * NV + idx;
        float4 q4 = (c == 0) ? fH4 : (c == 1) ? fW4 : fD4;
        const float* qf = &q4.x;
        float4 qhm4 = hm ? ld4(cur + off - WD) : q4;
        float4 qhp4 = hp ? ld4(cur + off + WD) : q4;
        float4 qwm4 = wm ? ld4(cur + off - DD) : q4;
        float4 qwp4 = wp ? ld4(cur + off + DD) : q4;
        float leftS  = dmL ? cur[off - 1] : 0.f;
        float rightS = dpR ? cur[off + 4] : 0.f;
        const float* qhmf = &qhm4.x; const float* qhpf = &qhp4.x;
        const float* qwmf = &qwm4.x; const float* qwpf = &qwp4.x;

        float4 m4 = ld4(g_m + off);
        float4 v4 = ld4(g_v + off);
        float4 vh4 = ld4(g_vh + off);
        float* mf = &m4.x; float* vf = &v4.x; float* vhf = &vh4.x;
        float4 out4;
        float* of = &out4.x;
        const float* dint = (c == 0) ? dch : (c == 1) ? dcw : dcd;

#pragma unroll
        for (int l = 0; l < 4; l++) {
            int d = d0 + l;
            float fc = qf[l];
            float tH = 0.f, tW = 0.f, tD = 0.f;
            if (hm) tH += fc - qhmf[l];
            if (hp) tH -= qhpf[l] - fc;
            if (wm) tW += fc - qwmf[l];
            if (wp) tW -= qwpf[l] - fc;
            if (d > 0) {
                float nb = (l == 0) ? leftS : qf[l - 1];
                tD += fc - nb;
            }
            if (d < DD - 1) {
                float nb = (l == 3) ? rightS : qf[l + 1];
                tD -= nb - fc;
            }
            float g = gi[l] * dint[l] + coefH * tH + coefW * tW + coefD * tD;

            float m = 0.9f * mf[l] + 0.1f * g;
            float v = 0.999f * vf[l] + 0.001f * g * g;
            float vh = fmaxf(vhf[l], v);
            mf[l] = m; vf[l] = v; vhf[l] = vh;
            float m_hat = m / bc1;
            float denom = sqrtf(vh) / sbc2 + 1e-8f;
            of[l] = fc - 0.1f * m_hat / denom;
        }
        st4(g_m + off, m4);
        st4(g_v + off, v4);
        st4(g_vh + off, vh4);
        st4(nxt + off, out4);
    }
}

// ---------------------------------------------------------------------------
// Final MSE: deterministic two-stage reduction (double accumulation).
__global__ void k_mse_part4(const float* __restrict__ f0, int finalB) {
    const float* __restrict__ flow = finalB ? g_flowB : g_flowA;
    __shared__ double sd[256];
    double acc = 0.0;
    int stride = gridDim.x * blockDim.x;
    for (int i = blockIdx.x * blockDim.x + threadIdx.x; i < NV3 / 4; i += stride) {
        float4 a = ld4(flow + i * 4);
        float4 b = ld4(f0 + i * 4);
        float dx = a.x - b.x, dy = a.y - b.y, dz = a.z - b.z, dw = a.w - b.w;
        acc += (double)dx * dx + (double)dy * dy + (double)dz * dz + (double)dw * dw;
    }
    sd[threadIdx.x] = acc;
    __syncthreads();
    for (int st = 128; st > 0; st >>= 1) {
        if (threadIdx.x < st) sd[threadIdx.x] += sd[threadIdx.x + st];
        __syncthreads();
    }
    if (threadIdx.x == 0) g_part[blockIdx.x] = sd[0];
}

__global__ void k_mse_final(float* __restrict__ out) {
    __shared__ double sd[256];
    double acc = 0.0;
    for (int i = threadIdx.x; i < RED_BLOCKS; i += 256) acc += g_part[i];
    sd[threadIdx.x] = acc;
    __syncthreads();
    for (int st = 128; st > 0; st >>= 1) {
        if (threadIdx.x < st) sd[threadIdx.x] += sd[threadIdx.x + st];
        __syncthreads();
    }
    if (threadIdx.x == 0) out[0] = (float)(sd[0] / (double)NV3);
}

// ---------------------------------------------------------------------------
extern "C" void kernel_launch(void* const* d_in, const int* in_sizes, int n_in,
                              void* d_out, int out_size) {
    const float* x  = (const float*)d_in[0];
    const float* y  = (const float*)d_in[1];
    const float* f0 = (const float*)d_in[2];
    float* out = (float*)d_out;
    (void)in_sizes; (void)n_in; (void)out_size;

    const int NB4  = (NV / 4 + 255) / 256;     // 4800
    const int NB34 = (NV3 / 4 + 255) / 256;    // 14400
    const int NBW  = (RS4_W + 255) / 256;      // 300
    const int NBH  = (RS4_H + 255) / 256;      // 300

    k_init4<<<NB34, 256>>>(f0);

    // Precompute J window sums (constant across Adam steps)
    k_convD_J<<<HH * WW, DD>>>(y);
    k_convW2_rs4<<<NBW, 256>>>();
    k_convH2_rs4<<<NBH, 256>>>();

    for (int t = 1; t <= 5; t++) {
        int parity = (t - 1) & 1;
        k_warp_convDf<<<HH * WW, DD>>>(x, y, parity);   // -> t0 (I,I2,IJ D-conv), g_I
        k_convW3_rs4<<<NBW, 256>>>(0);                  // t0 -> t1
        k_convH_coeff_rs4<<<NBH, 256>>>();              // t1 -> t0 (gA,gC,gE)
        k_convD_3v<<<HH * WW / 4, DD>>>();              // t0 -> t1
        k_convW3_rs4<<<NBW, 256>>>(1);                  // t1 -> t0
        k_convH_gI_rs4<<<NBH, 256>>>(y);                // t0 -> gI
        double bc1 = 1.0 - pow(0.9, (double)t);
        double bc2 = 1.0 - pow(0.999, (double)t);
        k_grad_adam4<<<NB4, 256>>>(x, parity, (float)bc1, (float)sqrt(bc2));
    }

    k_mse_part4<<<RED_BLOCKS, 256>>>(f0, 1);   // final flow in B after 5 iters
    k_mse_final<<<1, 256>>>(out);
}